// round 8
// baseline (speedup 1.0000x reference)
#include <cuda_runtime.h>
#include <cstdint>
#include <cstddef>

#define NS 64
#define MO 32
#define NSIG 129
#define TSTEPS 250
#define NTRAJ 128
#define NT 512
#define DTC 0.02f
#define NLAM 63.0f
#define CW (0.5f/63.0f)
#define WM0 (-1.0f/63.0f)
#define WC0 (2.0f - 1.0f/63.0f)
#define WDIFF (WC0 - CW)
#define WMD (WM0 - CW)
#define XS_OFF 2048000ULL
#define PS_SZ  131072000ULL

typedef unsigned long long ull;

__device__ __forceinline__ void fma2(ull &d, ull a, ull b) {
    asm("fma.rn.f32x2 %0, %1, %2, %0;" : "+l"(d) : "l"(a), "l"(b));
}
__device__ __forceinline__ float hsum2(ull v) {
    return __uint_as_float((unsigned)v) + __uint_as_float((unsigned)(v >> 32));
}
__device__ __forceinline__ ull ld2s(const float* p) { return *reinterpret_cast<const ull*>(p); }
__device__ __forceinline__ void st2s(float* p, ull v) { *reinterpret_cast<ull*>(p) = v; }
__device__ __forceinline__ ull pk2(float x) {
    ull r; asm("mov.b64 %0, {%1, %1};" : "=l"(r) : "f"(x)); return r;
}
__device__ __forceinline__ float tanh_fast(float x) {
    float r; asm("tanh.approx.f32 %0, %1;" : "=f"(r) : "f"(x)); return r;
}

struct SM {
    float F[NS][66];
    float H[MO][66];
    float Qs[NS][66];
    float Rs[MO][33];
    float P[NS][66];
    float Achol[NS][66];   // column-major: Achol[j][i] = NLAM*(P+eps)
    float Lc[NS][66];      // Lc[k][d] = L[d][k]
    float Gk[NS][66];      // Gk[k][d] = sum_e Lc[k][e]*F[d][e]
    float dxT[NS][130];    // raw sf, then centered; col 129 = pad(0)
    float dzT[MO][130];
    float Pz[MO][33];
    float Pxz[NS][34];
    float Usm[NS][34];
    float x[NS], xp[NS], innov[MO], zinv[MO], wsol[MO], row0[NS], yobs[MO];
    float binv[8];
    float red[16];
};

__device__ float g_mse[NTRAJ];
__device__ unsigned int g_ctr = 0;

__global__ __launch_bounds__(NT, 1)
void ukf_kernel(const float* __restrict__ gX, const float* __restrict__ gY,
                const float* __restrict__ gF, const float* __restrict__ gH,
                const float* __restrict__ gQ, const float* __restrict__ gR,
                float* __restrict__ out, int write_xs, int write_ps,
                unsigned long long osz)
{
    extern __shared__ unsigned char smem_raw[];
    SM& s = *reinterpret_cast<SM*>(smem_raw);
    const int tid = threadIdx.x;
    const int traj = blockIdx.x;

    // ---- init ----
    for (int idx = tid; idx < NS*NS; idx += NT) {
        int i = idx >> 6, j = idx & 63;
        s.F[i][j]  = gF[idx];
        s.Qs[i][j] = gQ[idx];
        s.Achol[j][i] = (i == j) ? NLAM * (1e-5f + 1e-8f) : 0.0f;
    }
    for (int idx = tid; idx < MO*NS; idx += NT) {
        int i = idx >> 6, j = idx & 63;
        s.H[i][j] = gH[idx];
    }
    for (int idx = tid; idx < MO*MO; idx += NT) {
        int i = idx >> 5, j = idx & 31;
        s.Rs[i][j] = gR[idx];
    }
    if (tid < NS) s.x[tid] = 0.0f;
    float mse_acc = 0.0f;

    for (int t = 0; t < TSTEPS; ++t) {
        // ======== phase 1: blocked Cholesky-64 (8x8 blocks) ========
        #pragma unroll 1
        for (int b = 0; b < 8; ++b) {
            const int j0 = 8 * b;
            if (tid < 64) {
                if (tid < 32) {
                    // --- diagonal block factor: registers + shuffles (lanes 0..7) ---
                    int r = tid;
                    float v[8];
                    #pragma unroll
                    for (int c = 0; c < 8; ++c)
                        v[c] = (r < 8) ? s.Achol[j0+c][j0+r] : 0.0f;
                    #pragma unroll
                    for (int jj = 0; jj < 8; ++jj) {
                        float piv = __shfl_sync(0xffffffffu, v[jj], jj);
                        float d = sqrtf(piv);
                        float l = v[jj] / d;
                        if (r < 8) s.Lc[j0+jj][j0+r] = (r >= jj) ? l : 0.0f;
                        if (r == jj) s.binv[jj] = 1.0f / d;
                        #pragma unroll
                        for (int c = jj+1; c < 8; ++c) {
                            float lc = __shfl_sync(0xffffffffu, l, c);
                            v[c] -= l * lc;
                        }
                    }
                }
                asm volatile("bar.sync 1, 64;" ::: "memory");
                // --- panel solve: one thread per row below the block ---
                int R = 56 - j0;
                if (tid < R) {
                    int rr = j0 + 8 + tid;
                    float a[8], sol[8];
                    #pragma unroll
                    for (int c = 0; c < 8; ++c) a[c] = s.Achol[j0+c][rr];
                    #pragma unroll
                    for (int jj = 0; jj < 8; ++jj) {
                        float tv = a[jj];
                        #pragma unroll
                        for (int q = 0; q < jj; ++q)
                            tv -= sol[q] * s.Lc[j0+q][j0+jj];
                        sol[jj] = tv * s.binv[jj];
                        s.Lc[j0+jj][rr] = sol[jj];
                    }
                }
            } else if (b == 0) {
                // zero Lc upper triangle (rows above each block) in parallel
                for (int idx = tid - 64; idx < 64*64; idx += NT - 64) {
                    int j = idx >> 6, d = idx & 63;
                    if (d < (j & ~7)) s.Lc[j][d] = 0.0f;
                }
            }
            __syncthreads();
            if (b < 7) {
                // --- trailing update: Achol[j][i] -= sum_p Lc[j0+p][i]*Lc[j0+p][j] ---
                const int jb = j0 + 8;
                const int C = 64 - jb;          // remaining cols/rows
                const int np = C >> 1;          // i-pairs
                const int ntask = C * np;
                for (int idx = tid; idx < ntask; idx += NT) {
                    int j  = jb + idx / np;
                    int ip = (jb >> 1) + idx % np;
                    ull acc = ld2s(&s.Achol[j][2*ip]);
                    #pragma unroll
                    for (int p = 0; p < 8; ++p)
                        fma2(acc, ld2s(&s.Lc[j0+p][2*ip]), pk2(-s.Lc[j0+p][j]));
                    st2s(&s.Achol[j][2*ip], acc);
                }
                __syncthreads();
            }
        }

        // ======== phase 2: Gk = Lc @ F^T; row0 = F@x; prefetch y ========
        {
            float yreg = 0.0f;
            if (tid < MO) yreg = gY[(size_t)traj * TSTEPS * MO + (size_t)t * MO + tid];
            int tk = tid & 15, td = tid >> 4;   // td 0..31
            ull acc[4][2];
            #pragma unroll
            for (int r = 0; r < 4; ++r) { acc[r][0] = 0ULL; acc[r][1] = 0ULL; }
            #pragma unroll 4
            for (int kp = 0; kp < 32; ++kp) {
                ull a0 = ld2s(&s.Lc[tk   ][2*kp]);
                ull a1 = ld2s(&s.Lc[tk+16][2*kp]);
                ull a2 = ld2s(&s.Lc[tk+32][2*kp]);
                ull a3 = ld2s(&s.Lc[tk+48][2*kp]);
                ull b0 = ld2s(&s.F[td   ][2*kp]);
                ull b1 = ld2s(&s.F[td+32][2*kp]);
                fma2(acc[0][0],a0,b0); fma2(acc[0][1],a0,b1);
                fma2(acc[1][0],a1,b0); fma2(acc[1][1],a1,b1);
                fma2(acc[2][0],a2,b0); fma2(acc[2][1],a2,b1);
                fma2(acc[3][0],a3,b0); fma2(acc[3][1],a3,b1);
            }
            #pragma unroll
            for (int r = 0; r < 4; ++r) {
                s.Gk[tk+16*r][td   ] = hsum2(acc[r][0]);
                s.Gk[tk+16*r][td+32] = hsum2(acc[r][1]);
            }
            if (tid < NS) {
                ull rc = 0ULL;
                #pragma unroll 4
                for (int kp = 0; kp < 32; ++kp)
                    fma2(rc, ld2s(&s.x[2*kp]), ld2s(&s.F[tid][2*kp]));
                s.row0[tid] = hsum2(rc);
            }
            if (tid < MO) s.yobs[tid] = yreg;
        }
        __syncthreads();

        // ======== phase 3: sf element-wise, stored transposed into dxT ========
        for (int idx = tid; idx < 130*NS; idx += NT) {
            int r = idx >> 6, d = idx & 63;
            float v;
            if (r == 129) v = 0.0f;
            else {
                float base = s.x[d], arg = s.row0[d];
                if (r >= 1) {
                    int k = (r <= NS) ? r - 1 : r - 1 - NS;
                    float lv = s.Lc[k][d], gv = s.Gk[k][d];
                    if (r <= NS) { base += lv; arg += gv; }
                    else         { base -= lv; arg -= gv; }
                }
                v = base + DTC * tanh_fast(arg);
            }
            s.dxT[d][r] = v;
        }
        __syncthreads();

        // ======== phase 4: xp via intra-warp reduce (1 barrier) ========
        {
            int d = tid >> 3, g = tid & 7;
            float acc0 = 0.f, acc1 = 0.f;
            for (int k = g; k <= 120; k += 16) {
                acc0 += s.dxT[d][k];
                acc1 += s.dxT[d][k+8];
            }
            if (g == 0) acc0 += s.dxT[d][128];
            float v = acc0 + acc1;
            v += __shfl_down_sync(0xffffffffu, v, 4, 8);
            v += __shfl_down_sync(0xffffffffu, v, 2, 8);
            v += __shfl_down_sync(0xffffffffu, v, 1, 8);
            if (g == 0) s.xp[d] = CW * v + WMD * s.dxT[d][0];
        }
        __syncthreads();

        // ======== phase 5: center dxT in place | warp0: innov = y - H@xp ========
        if (tid < 32) {
            ull acc = 0ULL;
            #pragma unroll 4
            for (int kp = 0; kp < 32; ++kp)
                fma2(acc, ld2s(&s.H[tid][2*kp]), ld2s(&s.xp[2*kp]));
            s.innov[tid] = s.yobs[tid] - hsum2(acc);
        } else {
            for (int idx = tid - 32; idx < 130*NS; idx += NT - 32) {
                int d = idx / 130, k = idx - d * 130;
                float v = (k < 129) ? s.dxT[d][k] - s.xp[d] : 0.0f;
                s.dxT[d][k] = v;
            }
        }
        __syncthreads();

        // ======== phase 6: dzT = H @ dx ========
        {
            int ti = tid & 15, g = tid >> 4;   // g 0..31
            ull a00=0ULL,a01=0ULL,a10=0ULL,a11=0ULL, e0=0ULL, e1=0ULL;
            bool extra = (g == 31);
            for (int d = 0; d < NS; ++d) {
                ull h0 = pk2(s.H[ti   ][d]);
                ull h1 = pk2(s.H[ti+16][d]);
                ull b0 = ld2s(&s.dxT[d][2*g]);
                ull b1 = ld2s(&s.dxT[d][2*(g+32)]);
                fma2(a00,h0,b0); fma2(a01,h0,b1);
                fma2(a10,h1,b0); fma2(a11,h1,b1);
                if (extra) {
                    ull b2 = ld2s(&s.dxT[d][128]);
                    fma2(e0,h0,b2); fma2(e1,h1,b2);
                }
            }
            st2s(&s.dzT[ti   ][2*g],      a00);
            st2s(&s.dzT[ti   ][2*(g+32)], a01);
            st2s(&s.dzT[ti+16][2*g],      a10);
            st2s(&s.dzT[ti+16][2*(g+32)], a11);
            if (extra) {
                st2s(&s.dzT[ti   ][128], e0);
                st2s(&s.dzT[ti+16][128], e1);
            }
        }
        __syncthreads();

        // ======== phase 7: Pz gram (2 outputs/thread) ========
        {
            int ti = tid & 15, tj = tid >> 4;   // tj 0..31
            ull a0 = 0ULL, a1 = 0ULL;
            #pragma unroll 2
            for (int kp = 0; kp < 65; ++kp) {
                ull b  = ld2s(&s.dzT[tj][2*kp]);
                fma2(a0, ld2s(&s.dzT[ti   ][2*kp]), b);
                fma2(a1, ld2s(&s.dzT[ti+16][2*kp]), b);
            }
            float bz = s.dzT[tj][0];
            s.Pz[ti   ][tj] = CW*hsum2(a0) + WDIFF * s.dzT[ti   ][0]*bz + s.Rs[ti   ][tj];
            s.Pz[ti+16][tj] = CW*hsum2(a1) + WDIFF * s.dzT[ti+16][0]*bz + s.Rs[ti+16][tj];
        }
        __syncthreads();

        // ======== phase 8: warp0 chol32(Pz) | others P_pred + Pxz grams ========
        if (tid < 32) {
            int lane = tid;
            for (int j = 0; j < MO; ++j) {
                float c = 0.0f;
                if (lane >= j) {
                    c = s.Pz[lane][j];
                    float c0=0.f, c1=0.f; int k = 0;
                    for (; k + 1 < j; k += 2) {
                        c0 += s.Pz[lane][k]   * s.Pz[j][k];
                        c1 += s.Pz[lane][k+1] * s.Pz[j][k+1];
                    }
                    if (k < j) c0 += s.Pz[lane][k] * s.Pz[j][k];
                    c -= c0 + c1;
                }
                float cj = __shfl_sync(0xffffffffu, c, j);
                float d = sqrtf(cj);
                if (lane == j)      { s.Pz[j][j] = d; s.zinv[j] = 1.0f / d; }
                else if (lane > j)  { s.Pz[lane][j] = c / d; }
                __syncwarp();
            }
        } else {
            for (int idx = tid - 32; idx < 1536; idx += NT - 32) {
                if (idx < 1024) {
                    int ti = idx & 31, tj = idx >> 5;
                    ull a00=0ULL,a01=0ULL,a10=0ULL,a11=0ULL;
                    #pragma unroll 2
                    for (int kp = 0; kp < 65; ++kp) {
                        ull r0 = ld2s(&s.dxT[ti   ][2*kp]);
                        ull r1 = ld2s(&s.dxT[ti+32][2*kp]);
                        ull c0 = ld2s(&s.dxT[tj   ][2*kp]);
                        ull c1 = ld2s(&s.dxT[tj+32][2*kp]);
                        fma2(a00,r0,c0); fma2(a01,r0,c1);
                        fma2(a10,r1,c0); fma2(a11,r1,c1);
                    }
                    float x0 = s.dxT[ti][0], x1 = s.dxT[ti+32][0];
                    float y0 = s.dxT[tj][0], y1 = s.dxT[tj+32][0];
                    s.P[ti   ][tj   ] = CW*hsum2(a00) + WDIFF*x0*y0 + s.Qs[ti   ][tj   ];
                    s.P[ti   ][tj+32] = CW*hsum2(a01) + WDIFF*x0*y1 + s.Qs[ti   ][tj+32];
                    s.P[ti+32][tj   ] = CW*hsum2(a10) + WDIFF*x1*y0 + s.Qs[ti+32][tj   ];
                    s.P[ti+32][tj+32] = CW*hsum2(a11) + WDIFF*x1*y1 + s.Qs[ti+32][tj+32];
                } else {
                    int q = idx - 1024;
                    int ti = q & 31, tj = q >> 5;   // tj 0..15
                    ull a00=0ULL,a01=0ULL,a10=0ULL,a11=0ULL;
                    #pragma unroll 2
                    for (int kp = 0; kp < 65; ++kp) {
                        ull r0 = ld2s(&s.dxT[ti   ][2*kp]);
                        ull r1 = ld2s(&s.dxT[ti+32][2*kp]);
                        ull c0 = ld2s(&s.dzT[tj   ][2*kp]);
                        ull c1 = ld2s(&s.dzT[tj+16][2*kp]);
                        fma2(a00,r0,c0); fma2(a01,r0,c1);
                        fma2(a10,r1,c0); fma2(a11,r1,c1);
                    }
                    float x0 = s.dxT[ti][0], x1 = s.dxT[ti+32][0];
                    float z0 = s.dzT[tj][0], z1 = s.dzT[tj+16][0];
                    s.Pxz[ti   ][tj   ] = CW*hsum2(a00) + WDIFF*x0*z0;
                    s.Pxz[ti   ][tj+16] = CW*hsum2(a01) + WDIFF*x0*z1;
                    s.Pxz[ti+32][tj   ] = CW*hsum2(a10) + WDIFF*x1*z0;
                    s.Pxz[ti+32][tj+16] = CW*hsum2(a11) + WDIFF*x1*z1;
                }
            }
        }
        __syncthreads();

        // ======== phase 9: forward solves L*[U|w] = [Pxz^T|innov] ========
        if (tid < NS + 1) {
            float v[MO];
            if (tid < NS) {
                #pragma unroll
                for (int m = 0; m < MO; ++m) v[m] = s.Pxz[tid][m];
            } else {
                #pragma unroll
                for (int m = 0; m < MO; ++m) v[m] = s.innov[m];
            }
            #pragma unroll
            for (int i = 0; i < MO; ++i) {
                float acc = v[i];
                #pragma unroll
                for (int j = 0; j < i; ++j) acc -= s.Pz[i][j] * v[j];
                v[i] = acc * s.zinv[i];
            }
            if (tid < NS) {
                #pragma unroll
                for (int m = 0; m < MO; ++m) s.Usm[tid][m] = v[m];
            } else {
                #pragma unroll
                for (int m = 0; m < MO; ++m) s.wsol[m] = v[m];
            }
        }
        __syncthreads();

        // ======== phase 10: x_new + (P_new = P - U^T U) -> next Achol ========
        if (tid < NS) {
            float xn = s.xp[tid];
            #pragma unroll
            for (int m = 0; m < MO; ++m) xn += s.Usm[tid][m] * s.wsol[m];
            s.x[tid] = xn;
            size_t oidx = ((size_t)traj * TSTEPS + t) * NS + tid;
            if (write_xs) out[oidx] = xn;
            float de = xn - gX[oidx];
            mse_acc += de * de;
        }
        {
            int ti = tid & 31, tj = tid >> 5;   // tj 0..15
            ull acc[2][4];
            #pragma unroll
            for (int r = 0; r < 2; ++r)
                #pragma unroll
                for (int c = 0; c < 4; ++c) acc[r][c] = 0ULL;
            #pragma unroll 4
            for (int mp = 0; mp < 16; ++mp) {
                ull r0 = ld2s(&s.Usm[ti   ][2*mp]);
                ull r1 = ld2s(&s.Usm[ti+32][2*mp]);
                ull c0 = ld2s(&s.Usm[tj   ][2*mp]);
                ull c1 = ld2s(&s.Usm[tj+16][2*mp]);
                ull c2 = ld2s(&s.Usm[tj+32][2*mp]);
                ull c3 = ld2s(&s.Usm[tj+48][2*mp]);
                fma2(acc[0][0],r0,c0); fma2(acc[0][1],r0,c1); fma2(acc[0][2],r0,c2); fma2(acc[0][3],r0,c3);
                fma2(acc[1][0],r1,c0); fma2(acc[1][1],r1,c1); fma2(acc[1][2],r1,c2); fma2(acc[1][3],r1,c3);
            }
            #pragma unroll
            for (int r = 0; r < 2; ++r)
                #pragma unroll
                for (int c = 0; c < 4; ++c) {
                    int i = ti + 32*r, j = tj + 16*c;
                    float pv = s.P[i][j] - hsum2(acc[r][c]);
                    s.Achol[j][i] = NLAM * (pv + ((i == j) ? 1e-8f : 0.0f));
                    if (write_ps)
                        out[XS_OFF + (((size_t)traj * TSTEPS + t) << 12) + (size_t)i*NS + j] = pv;
                }
        }
        __syncthreads();
    }

    // ---- per-trajectory MSE + merged finalize ----
    {
        float v = (tid < NS) ? mse_acc : 0.0f;
        for (int o = 16; o > 0; o >>= 1) v += __shfl_down_sync(0xffffffffu, v, o);
        if ((tid & 31) == 0) s.red[tid >> 5] = v;
        __syncthreads();
        if (tid == 0) {
            g_mse[traj] = (s.red[0] + s.red[1]) * (1.0f / (float)(TSTEPS * NS));
            __threadfence();
            unsigned int prev = atomicAdd(&g_ctr, 1u);
            if (prev == NTRAJ - 1) {
                __threadfence();
                float tot = 0.0f;
                for (int i = 0; i < NTRAJ; ++i) tot += g_mse[i];
                float lin = tot / (float)NTRAJ;
                float db = 10.0f * log10f(lin);
                const unsigned long long XS = XS_OFF, PS = PS_SZ;
                if (osz >= XS + PS + 2ULL)      { out[XS+PS] = lin; out[XS+PS+1ULL] = db; }
                else if (osz == XS + 2ULL)      { out[XS] = lin; out[XS+1ULL] = db; }
                else if (osz == 2ULL)           { out[0] = lin; out[1] = db; }
                else if (osz == 1ULL)           { out[0] = db; }
                atomicExch(&g_ctr, 0u);
            }
        }
    }
}

extern "C" void kernel_launch(void* const* d_in, const int* in_sizes, int n_in,
                              void* d_out, int out_size)
{
    const float* X = (const float*)d_in[0];
    const float* Y = (const float*)d_in[1];
    const float* F = (const float*)d_in[2];
    const float* H = (const float*)d_in[3];
    const float* Q = (const float*)d_in[4];
    const float* R = (const float*)d_in[5];
    float* out = (float*)d_out;

    unsigned long long os = (unsigned long long)(long long)out_size;
    int wxs = (os >= XS_OFF) ? 1 : 0;
    int wps = (os >= XS_OFF + PS_SZ) ? 1 : 0;

    cudaFuncSetAttribute(ukf_kernel, cudaFuncAttributeMaxDynamicSharedMemorySize,
                         (int)sizeof(SM));
    ukf_kernel<<<NTRAJ, NT, sizeof(SM)>>>(X, Y, F, H, Q, R, out, wxs, wps, os);
}

// round 10
// speedup vs baseline: 1.2466x; 1.2466x over previous
#include <cuda_runtime.h>
#include <cstdint>
#include <cstddef>

#define NS 64
#define MO 32
#define NSIG 129
#define TSTEPS 250
#define NTRAJ 128
#define NT 512
#define DTC 0.02f
#define NLAM 63.0f
#define CW (0.5f/63.0f)
#define WM0 (-1.0f/63.0f)
#define WC0 (2.0f - 1.0f/63.0f)
#define WDIFF (WC0 - CW)
#define WMD (WM0 - CW)
#define XS_OFF 2048000ULL
#define PS_SZ  131072000ULL

typedef unsigned long long ull;

__device__ __forceinline__ void fma2(ull &d, ull a, ull b) {
    asm("fma.rn.f32x2 %0, %1, %2, %0;" : "+l"(d) : "l"(a), "l"(b));
}
__device__ __forceinline__ float hsum2(ull v) {
    return __uint_as_float((unsigned)v) + __uint_as_float((unsigned)(v >> 32));
}
__device__ __forceinline__ ull ld2s(const float* p) { return *reinterpret_cast<const ull*>(p); }
__device__ __forceinline__ void st2s(float* p, ull v) { *reinterpret_cast<ull*>(p) = v; }
__device__ __forceinline__ ull pk2(float x) {
    ull r; asm("mov.b64 %0, {%1, %1};" : "=l"(r) : "f"(x)); return r;
}
__device__ __forceinline__ float tanh_fast(float x) {
    float r; asm("tanh.approx.f32 %0, %1;" : "=f"(r) : "f"(x)); return r;
}

struct SM {
    float F[NS][66];
    float H[MO][66];
    float Qs[NS][66];
    float Rs[MO][33];
    float P[NS][66];
    float Achol[NS][66];   // column-major: Achol[j][i] = NLAM*(P+eps)
    float Lc[NS][66];      // Lc[k][d] = L[d][k]
    float Gk[NS][66];      // Gk[k][d] = sum_e Lc[k][e]*F[d][e]
    float dxT[NS][130];    // raw sf, then centered; col 129 = pad(0)
    float dzT[MO][130];
    float Pz[MO][33];
    float Pxz[NS][34];
    float Usm[NS][34];
    float x[NS], xp[NS], innov[MO], zinv[MO], wsol[MO], row0[NS], yobs[MO];
    float red[16];
};

__device__ float g_mse[NTRAJ];
__device__ unsigned int g_ctr = 0;

__global__ __launch_bounds__(NT, 1)
void ukf_kernel(const float* __restrict__ gX, const float* __restrict__ gY,
                const float* __restrict__ gF, const float* __restrict__ gH,
                const float* __restrict__ gQ, const float* __restrict__ gR,
                float* __restrict__ out, int write_xs, int write_ps,
                unsigned long long osz)
{
    extern __shared__ unsigned char smem_raw[];
    SM& s = *reinterpret_cast<SM*>(smem_raw);
    const int tid = threadIdx.x;
    const int traj = blockIdx.x;

    // ---- init ----
    for (int idx = tid; idx < NS*NS; idx += NT) {
        int i = idx >> 6, j = idx & 63;
        s.F[i][j]  = gF[idx];
        s.Qs[i][j] = gQ[idx];
        s.Achol[j][i] = (i == j) ? NLAM * (1e-5f + 1e-8f) : 0.0f;
    }
    for (int idx = tid; idx < MO*NS; idx += NT) {
        int i = idx >> 6, j = idx & 63;
        s.H[i][j] = gH[idx];
    }
    for (int idx = tid; idx < MO*MO; idx += NT) {
        int i = idx >> 5, j = idx & 31;
        s.Rs[i][j] = gR[idx];
    }
    if (tid < NS) s.x[tid] = 0.0f;
    float mse_acc = 0.0f;

    for (int t = 0; t < TSTEPS; ++t) {
        // ======== phase 1: rank-2 right-looking Cholesky-64 (32 barriers) ========
        {
            const int kk = tid & 63, pp = tid >> 6;   // pp 0..7
            #pragma unroll 1
            for (int j = 0; j < NS; j += 2) {
                __syncthreads();
                // broadcast scalars (all threads)
                float a00 = s.Achol[j][j];
                float a01 = s.Achol[j][j+1];
                float a11 = s.Achol[j+1][j+1];
                float inv00 = 1.0f / a00;
                float r01 = a01 * inv00;
                float a11p = a11 - a01 * r01;
                float inv11 = 1.0f / a11p;
                float d0 = sqrtf(a00);
                float d1 = sqrtf(a11p);
                // extract L columns j, j+1 (threads 0..63 are rows)
                if (tid < NS) {
                    float aj  = s.Achol[j][tid];
                    float aj1 = s.Achol[j+1][tid] - r01 * aj;
                    s.Lc[j][tid]   = (tid >= j)     ? aj  / d0 : 0.0f;
                    s.Lc[j+1][tid] = (tid >= j + 1) ? aj1 / d1 : 0.0f;
                }
                // rank-2 trailing update of columns kk > j+1
                if (kk > j + 1) {
                    float b0 = s.Achol[j][kk];
                    float b1 = s.Achol[j+1][kk] - r01 * b0;
                    float c0 = b0 * inv00;
                    float c1 = b1 * inv11;
                    ull m0 = pk2(-(c0 - c1 * r01));
                    ull m1 = pk2(-c1);
                    #pragma unroll
                    for (int p = pp; p < 32; p += 8) {
                        ull cur = ld2s(&s.Achol[kk][2*p]);
                        fma2(cur, ld2s(&s.Achol[j  ][2*p]), m0);
                        fma2(cur, ld2s(&s.Achol[j+1][2*p]), m1);
                        st2s(&s.Achol[kk][2*p], cur);
                    }
                }
            }
        }
        __syncthreads();

        // ======== phase 2: Gk = Lc @ F^T; row0 = F@x; prefetch y ========
        {
            float yreg = 0.0f;
            if (tid < MO) yreg = gY[(size_t)traj * TSTEPS * MO + (size_t)t * MO + tid];
            int tk = tid & 15, td = tid >> 4;   // td 0..31
            ull acc[4][2];
            #pragma unroll
            for (int r = 0; r < 4; ++r) { acc[r][0] = 0ULL; acc[r][1] = 0ULL; }
            #pragma unroll 4
            for (int kp = 0; kp < 32; ++kp) {
                ull a0 = ld2s(&s.Lc[tk   ][2*kp]);
                ull a1 = ld2s(&s.Lc[tk+16][2*kp]);
                ull a2 = ld2s(&s.Lc[tk+32][2*kp]);
                ull a3 = ld2s(&s.Lc[tk+48][2*kp]);
                ull b0 = ld2s(&s.F[td   ][2*kp]);
                ull b1 = ld2s(&s.F[td+32][2*kp]);
                fma2(acc[0][0],a0,b0); fma2(acc[0][1],a0,b1);
                fma2(acc[1][0],a1,b0); fma2(acc[1][1],a1,b1);
                fma2(acc[2][0],a2,b0); fma2(acc[2][1],a2,b1);
                fma2(acc[3][0],a3,b0); fma2(acc[3][1],a3,b1);
            }
            #pragma unroll
            for (int r = 0; r < 4; ++r) {
                s.Gk[tk+16*r][td   ] = hsum2(acc[r][0]);
                s.Gk[tk+16*r][td+32] = hsum2(acc[r][1]);
            }
            if (tid < NS) {
                ull rc = 0ULL;
                #pragma unroll 4
                for (int kp = 0; kp < 32; ++kp)
                    fma2(rc, ld2s(&s.x[2*kp]), ld2s(&s.F[tid][2*kp]));
                s.row0[tid] = hsum2(rc);
            }
            if (tid < MO) s.yobs[tid] = yreg;
        }
        __syncthreads();

        // ======== phase 3: sf element-wise, stored transposed into dxT ========
        for (int idx = tid; idx < 130*NS; idx += NT) {
            int r = idx >> 6, d = idx & 63;
            float v;
            if (r == 129) v = 0.0f;
            else {
                float base = s.x[d], arg = s.row0[d];
                if (r >= 1) {
                    int k = (r <= NS) ? r - 1 : r - 1 - NS;
                    float lv = s.Lc[k][d], gv = s.Gk[k][d];
                    if (r <= NS) { base += lv; arg += gv; }
                    else         { base -= lv; arg -= gv; }
                }
                v = base + DTC * tanh_fast(arg);
            }
            s.dxT[d][r] = v;
        }
        __syncthreads();

        // ======== phase 4: xp via intra-warp reduce (1 barrier) ========
        {
            int d = tid >> 3, g = tid & 7;
            float acc0 = 0.f, acc1 = 0.f;
            for (int k = g; k <= 120; k += 16) {
                acc0 += s.dxT[d][k];
                acc1 += s.dxT[d][k+8];
            }
            if (g == 0) acc0 += s.dxT[d][128];
            float v = acc0 + acc1;
            v += __shfl_down_sync(0xffffffffu, v, 4, 8);
            v += __shfl_down_sync(0xffffffffu, v, 2, 8);
            v += __shfl_down_sync(0xffffffffu, v, 1, 8);
            if (g == 0) s.xp[d] = CW * v + WMD * s.dxT[d][0];
        }
        __syncthreads();

        // ======== phase 5: center dxT in place | warp0: innov = y - H@xp ========
        if (tid < 32) {
            ull acc = 0ULL;
            #pragma unroll 4
            for (int kp = 0; kp < 32; ++kp)
                fma2(acc, ld2s(&s.H[tid][2*kp]), ld2s(&s.xp[2*kp]));
            s.innov[tid] = s.yobs[tid] - hsum2(acc);
        } else {
            for (int idx = tid - 32; idx < 130*NS; idx += NT - 32) {
                int d = idx / 130, k = idx - d * 130;
                float v = (k < 129) ? s.dxT[d][k] - s.xp[d] : 0.0f;
                s.dxT[d][k] = v;
            }
        }
        __syncthreads();

        // ======== phase 6: dzT = H @ dx ========
        {
            int ti = tid & 15, g = tid >> 4;   // g 0..31
            ull a00=0ULL,a01=0ULL,a10=0ULL,a11=0ULL, e0=0ULL, e1=0ULL;
            bool extra = (g == 31);
            for (int d = 0; d < NS; ++d) {
                ull h0 = pk2(s.H[ti   ][d]);
                ull h1 = pk2(s.H[ti+16][d]);
                ull b0 = ld2s(&s.dxT[d][2*g]);
                ull b1 = ld2s(&s.dxT[d][2*(g+32)]);
                fma2(a00,h0,b0); fma2(a01,h0,b1);
                fma2(a10,h1,b0); fma2(a11,h1,b1);
                if (extra) {
                    ull b2 = ld2s(&s.dxT[d][128]);
                    fma2(e0,h0,b2); fma2(e1,h1,b2);
                }
            }
            st2s(&s.dzT[ti   ][2*g],      a00);
            st2s(&s.dzT[ti   ][2*(g+32)], a01);
            st2s(&s.dzT[ti+16][2*g],      a10);
            st2s(&s.dzT[ti+16][2*(g+32)], a11);
            if (extra) {
                st2s(&s.dzT[ti   ][128], e0);
                st2s(&s.dzT[ti+16][128], e1);
            }
        }
        __syncthreads();

        // ======== phase 7: Pz gram (2 outputs/thread) ========
        {
            int ti = tid & 15, tj = tid >> 4;   // tj 0..31
            ull a0 = 0ULL, a1 = 0ULL;
            #pragma unroll 2
            for (int kp = 0; kp < 65; ++kp) {
                ull b  = ld2s(&s.dzT[tj][2*kp]);
                fma2(a0, ld2s(&s.dzT[ti   ][2*kp]), b);
                fma2(a1, ld2s(&s.dzT[ti+16][2*kp]), b);
            }
            float bz = s.dzT[tj][0];
            s.Pz[ti   ][tj] = CW*hsum2(a0) + WDIFF * s.dzT[ti   ][0]*bz + s.Rs[ti   ][tj];
            s.Pz[ti+16][tj] = CW*hsum2(a1) + WDIFF * s.dzT[ti+16][0]*bz + s.Rs[ti+16][tj];
        }
        __syncthreads();

        // ======== phase 8: warp0 chol32(Pz) | others P_pred + Pxz grams ========
        if (tid < 32) {
            int lane = tid;
            for (int j = 0; j < MO; ++j) {
                float c = 0.0f;
                if (lane >= j) {
                    c = s.Pz[lane][j];
                    float c0=0.f, c1=0.f; int k = 0;
                    for (; k + 1 < j; k += 2) {
                        c0 += s.Pz[lane][k]   * s.Pz[j][k];
                        c1 += s.Pz[lane][k+1] * s.Pz[j][k+1];
                    }
                    if (k < j) c0 += s.Pz[lane][k] * s.Pz[j][k];
                    c -= c0 + c1;
                }
                float cj = __shfl_sync(0xffffffffu, c, j);
                float d = sqrtf(cj);
                if (lane == j)      { s.Pz[j][j] = d; s.zinv[j] = 1.0f / d; }
                else if (lane > j)  { s.Pz[lane][j] = c / d; }
                __syncwarp();
            }
        } else {
            for (int idx = tid - 32; idx < 1536; idx += NT - 32) {
                if (idx < 1024) {
                    int ti = idx & 31, tj = idx >> 5;
                    ull a00=0ULL,a01=0ULL,a10=0ULL,a11=0ULL;
                    #pragma unroll 2
                    for (int kp = 0; kp < 65; ++kp) {
                        ull r0 = ld2s(&s.dxT[ti   ][2*kp]);
                        ull r1 = ld2s(&s.dxT[ti+32][2*kp]);
                        ull c0 = ld2s(&s.dxT[tj   ][2*kp]);
                        ull c1 = ld2s(&s.dxT[tj+32][2*kp]);
                        fma2(a00,r0,c0); fma2(a01,r0,c1);
                        fma2(a10,r1,c0); fma2(a11,r1,c1);
                    }
                    float x0 = s.dxT[ti][0], x1 = s.dxT[ti+32][0];
                    float y0 = s.dxT[tj][0], y1 = s.dxT[tj+32][0];
                    s.P[ti   ][tj   ] = CW*hsum2(a00) + WDIFF*x0*y0 + s.Qs[ti   ][tj   ];
                    s.P[ti   ][tj+32] = CW*hsum2(a01) + WDIFF*x0*y1 + s.Qs[ti   ][tj+32];
                    s.P[ti+32][tj   ] = CW*hsum2(a10) + WDIFF*x1*y0 + s.Qs[ti+32][tj   ];
                    s.P[ti+32][tj+32] = CW*hsum2(a11) + WDIFF*x1*y1 + s.Qs[ti+32][tj+32];
                } else {
                    int q = idx - 1024;
                    int ti = q & 31, tj = q >> 5;   // tj 0..15
                    ull a00=0ULL,a01=0ULL,a10=0ULL,a11=0ULL;
                    #pragma unroll 2
                    for (int kp = 0; kp < 65; ++kp) {
                        ull r0 = ld2s(&s.dxT[ti   ][2*kp]);
                        ull r1 = ld2s(&s.dxT[ti+32][2*kp]);
                        ull c0 = ld2s(&s.dzT[tj   ][2*kp]);
                        ull c1 = ld2s(&s.dzT[tj+16][2*kp]);
                        fma2(a00,r0,c0); fma2(a01,r0,c1);
                        fma2(a10,r1,c0); fma2(a11,r1,c1);
                    }
                    float x0 = s.dxT[ti][0], x1 = s.dxT[ti+32][0];
                    float z0 = s.dzT[tj][0], z1 = s.dzT[tj+16][0];
                    s.Pxz[ti   ][tj   ] = CW*hsum2(a00) + WDIFF*x0*z0;
                    s.Pxz[ti   ][tj+16] = CW*hsum2(a01) + WDIFF*x0*z1;
                    s.Pxz[ti+32][tj   ] = CW*hsum2(a10) + WDIFF*x1*z0;
                    s.Pxz[ti+32][tj+16] = CW*hsum2(a11) + WDIFF*x1*z1;
                }
            }
        }
        __syncthreads();

        // ======== phase 9: forward solves L*[U|w] = [Pxz^T|innov] ========
        if (tid < NS + 1) {
            float v[MO];
            if (tid < NS) {
                #pragma unroll
                for (int m = 0; m < MO; ++m) v[m] = s.Pxz[tid][m];
            } else {
                #pragma unroll
                for (int m = 0; m < MO; ++m) v[m] = s.innov[m];
            }
            #pragma unroll
            for (int i = 0; i < MO; ++i) {
                float c0 = v[i], c1 = 0.0f;
                #pragma unroll
                for (int j = 0; j + 1 < i; j += 2) {
                    c0 -= s.Pz[i][j]   * v[j];
                    c1 += s.Pz[i][j+1] * v[j+1];
                }
                if (i & 1) c0 -= s.Pz[i][i-1] * v[i-1];
                v[i] = (c0 - c1) * s.zinv[i];
            }
            if (tid < NS) {
                #pragma unroll
                for (int m = 0; m < MO; ++m) s.Usm[tid][m] = v[m];
            } else {
                #pragma unroll
                for (int m = 0; m < MO; ++m) s.wsol[m] = v[m];
            }
        }
        __syncthreads();

        // ======== phase 10: x_new + (P_new = P - U^T U) -> next Achol ========
        if (tid < NS) {
            float xn = s.xp[tid];
            #pragma unroll
            for (int m = 0; m < MO; ++m) xn += s.Usm[tid][m] * s.wsol[m];
            s.x[tid] = xn;
            size_t oidx = ((size_t)traj * TSTEPS + t) * NS + tid;
            if (write_xs) out[oidx] = xn;
            float de = xn - gX[oidx];
            mse_acc += de * de;
        }
        {
            int ti = tid & 31, tj = tid >> 5;   // tj 0..15
            ull acc[2][4];
            #pragma unroll
            for (int r = 0; r < 2; ++r)
                #pragma unroll
                for (int c = 0; c < 4; ++c) acc[r][c] = 0ULL;
            #pragma unroll 4
            for (int mp = 0; mp < 16; ++mp) {
                ull r0 = ld2s(&s.Usm[ti   ][2*mp]);
                ull r1 = ld2s(&s.Usm[ti+32][2*mp]);
                ull c0 = ld2s(&s.Usm[tj   ][2*mp]);
                ull c1 = ld2s(&s.Usm[tj+16][2*mp]);
                ull c2 = ld2s(&s.Usm[tj+32][2*mp]);
                ull c3 = ld2s(&s.Usm[tj+48][2*mp]);
                fma2(acc[0][0],r0,c0); fma2(acc[0][1],r0,c1); fma2(acc[0][2],r0,c2); fma2(acc[0][3],r0,c3);
                fma2(acc[1][0],r1,c0); fma2(acc[1][1],r1,c1); fma2(acc[1][2],r1,c2); fma2(acc[1][3],r1,c3);
            }
            #pragma unroll
            for (int r = 0; r < 2; ++r)
                #pragma unroll
                for (int c = 0; c < 4; ++c) {
                    int i = ti + 32*r, j = tj + 16*c;
                    float pv = s.P[i][j] - hsum2(acc[r][c]);
                    s.Achol[j][i] = NLAM * (pv + ((i == j) ? 1e-8f : 0.0f));
                    if (write_ps)
                        out[XS_OFF + (((size_t)traj * TSTEPS + t) << 12) + (size_t)i*NS + j] = pv;
                }
        }
        __syncthreads();
    }

    // ---- per-trajectory MSE + merged finalize ----
    {
        float v = (tid < NS) ? mse_acc : 0.0f;
        for (int o = 16; o > 0; o >>= 1) v += __shfl_down_sync(0xffffffffu, v, o);
        if ((tid & 31) == 0) s.red[tid >> 5] = v;
        __syncthreads();
        if (tid == 0) {
            g_mse[traj] = (s.red[0] + s.red[1]) * (1.0f / (float)(TSTEPS * NS));
            __threadfence();
            unsigned int prev = atomicAdd(&g_ctr, 1u);
            if (prev == NTRAJ - 1) {
                __threadfence();
                float tot = 0.0f;
                for (int i = 0; i < NTRAJ; ++i) tot += g_mse[i];
                float lin = tot / (float)NTRAJ;
                float db = 10.0f * log10f(lin);
                const unsigned long long XS = XS_OFF, PS = PS_SZ;
                if (osz >= XS + PS + 2ULL)      { out[XS+PS] = lin; out[XS+PS+1ULL] = db; }
                else if (osz == XS + 2ULL)      { out[XS] = lin; out[XS+1ULL] = db; }
                else if (osz == 2ULL)           { out[0] = lin; out[1] = db; }
                else if (osz == 1ULL)           { out[0] = db; }
                atomicExch(&g_ctr, 0u);
            }
        }
    }
}

extern "C" void kernel_launch(void* const* d_in, const int* in_sizes, int n_in,
                              void* d_out, int out_size)
{
    const float* X = (const float*)d_in[0];
    const float* Y = (const float*)d_in[1];
    const float* F = (const float*)d_in[2];
    const float* H = (const float*)d_in[3];
    const float* Q = (const float*)d_in[4];
    const float* R = (const float*)d_in[5];
    float* out = (float*)d_out;

    unsigned long long os = (unsigned long long)(long long)out_size;
    int wxs = (os >= XS_OFF) ? 1 : 0;
    int wps = (os >= XS_OFF + PS_SZ) ? 1 : 0;

    cudaFuncSetAttribute(ukf_kernel, cudaFuncAttributeMaxDynamicSharedMemorySize,
                         (int)sizeof(SM));
    ukf_kernel<<<NTRAJ, NT, sizeof(SM)>>>(X, Y, F, H, Q, R, out, wxs, wps, os);
}

// round 11
// speedup vs baseline: 1.2817x; 1.0282x over previous
#include <cuda_runtime.h>
#include <cstdint>
#include <cstddef>

#define NS 64
#define MO 32
#define NSIG 129
#define TSTEPS 250
#define NTRAJ 128
#define NT 512
#define DTC 0.02f
#define NLAM 63.0f
#define CW (0.5f/63.0f)
#define WM0 (-1.0f/63.0f)
#define WC0 (2.0f - 1.0f/63.0f)
#define WDIFF (WC0 - CW)
#define WMD (WM0 - CW)
#define XS_OFF 2048000ULL
#define PS_SZ  131072000ULL

typedef unsigned long long ull;

__device__ __forceinline__ void fma2(ull &d, ull a, ull b) {
    asm("fma.rn.f32x2 %0, %1, %2, %0;" : "+l"(d) : "l"(a), "l"(b));
}
__device__ __forceinline__ float hsum2(ull v) {
    return __uint_as_float((unsigned)v) + __uint_as_float((unsigned)(v >> 32));
}
__device__ __forceinline__ ull ld2s(const float* p) { return *reinterpret_cast<const ull*>(p); }
__device__ __forceinline__ void st2s(float* p, ull v) { *reinterpret_cast<ull*>(p) = v; }
__device__ __forceinline__ ull pk2(float x) {
    ull r; asm("mov.b64 %0, {%1, %1};" : "=l"(r) : "f"(x)); return r;
}
__device__ __forceinline__ float tanh_fast(float x) {
    float r; asm("tanh.approx.f32 %0, %1;" : "=f"(r) : "f"(x)); return r;
}

struct SM {
    float F[NS][66];
    float H[MO][66];
    float Qs[NS][66];
    float Rs[MO][33];
    float P[NS][66];
    float Achol[NS][66];   // column-major: Achol[j][i] = NLAM*(P+eps)
    float Lc[NS][66];      // Lc[k][d] = L[d][k]
    float Gk[NS][66];      // Gk[k][d] = sum_e Lc[k][e]*F[d][e]
    float dxT[NS][130];    // raw sf, then centered; col 129 = pad(0)
    float dzT[MO][130];
    float Pz[MO][33];
    float Pxz[NS][34];
    float Usm[NS][34];
    float x[NS], xp[NS], innov[MO], zinv[MO], wsol[MO], row0[NS], yobs[MO];
    float red[16];
};

__device__ float g_mse[NTRAJ];
__device__ unsigned int g_ctr = 0;

__global__ __launch_bounds__(NT, 1)
void ukf_kernel(const float* __restrict__ gX, const float* __restrict__ gY,
                const float* __restrict__ gF, const float* __restrict__ gH,
                const float* __restrict__ gQ, const float* __restrict__ gR,
                float* __restrict__ out, int write_xs, int write_ps,
                unsigned long long osz)
{
    extern __shared__ unsigned char smem_raw[];
    SM& s = *reinterpret_cast<SM*>(smem_raw);
    const int tid = threadIdx.x;
    const int traj = blockIdx.x;

    // ---- init ----
    for (int idx = tid; idx < NS*NS; idx += NT) {
        int i = idx >> 6, j = idx & 63;
        s.F[i][j]  = gF[idx];
        s.Qs[i][j] = gQ[idx];
        s.Achol[j][i] = (i == j) ? NLAM * (1e-5f + 1e-8f) : 0.0f;
    }
    for (int idx = tid; idx < MO*NS; idx += NT) {
        int i = idx >> 6, j = idx & 63;
        s.H[i][j] = gH[idx];
    }
    for (int idx = tid; idx < MO*MO; idx += NT) {
        int i = idx >> 5, j = idx & 31;
        s.Rs[i][j] = gR[idx];
    }
    if (tid < NS) s.x[tid] = 0.0f;
    float mse_acc = 0.0f;

    for (int t = 0; t < TSTEPS; ++t) {
        // ======== phase 1: rank-2 right-looking Cholesky-64 (32 barriers) ========
        {
            const int kk = tid & 63, pp = tid >> 6;   // pp 0..7
            #pragma unroll 1
            for (int j = 0; j < NS; j += 2) {
                __syncthreads();
                float a00 = s.Achol[j][j];
                float a01 = s.Achol[j][j+1];
                float a11 = s.Achol[j+1][j+1];
                float inv00 = 1.0f / a00;
                float r01 = a01 * inv00;
                float a11p = a11 - a01 * r01;
                float inv11 = 1.0f / a11p;
                float d0 = sqrtf(a00);
                float d1 = sqrtf(a11p);
                if (tid < NS) {
                    float aj  = s.Achol[j][tid];
                    float aj1 = s.Achol[j+1][tid] - r01 * aj;
                    s.Lc[j][tid]   = (tid >= j)     ? aj  / d0 : 0.0f;
                    s.Lc[j+1][tid] = (tid >= j + 1) ? aj1 / d1 : 0.0f;
                }
                if (kk > j + 1) {
                    float b0 = s.Achol[j][kk];
                    float b1 = s.Achol[j+1][kk] - r01 * b0;
                    float c0 = b0 * inv00;
                    float c1 = b1 * inv11;
                    ull m0 = pk2(-(c0 - c1 * r01));
                    ull m1 = pk2(-c1);
                    #pragma unroll
                    for (int p = pp; p < 32; p += 8) {
                        ull cur = ld2s(&s.Achol[kk][2*p]);
                        fma2(cur, ld2s(&s.Achol[j  ][2*p]), m0);
                        fma2(cur, ld2s(&s.Achol[j+1][2*p]), m1);
                        st2s(&s.Achol[kk][2*p], cur);
                    }
                }
            }
        }
        __syncthreads();

        // ======== phase 2: Gk = Lc @ F^T; row0 = F@x; prefetch y ========
        {
            float yreg = 0.0f;
            if (tid < MO) yreg = gY[(size_t)traj * TSTEPS * MO + (size_t)t * MO + tid];
            int tk = tid & 15, td = tid >> 4;   // td 0..31
            ull acc[4][2];
            #pragma unroll
            for (int r = 0; r < 4; ++r) { acc[r][0] = 0ULL; acc[r][1] = 0ULL; }
            #pragma unroll 4
            for (int kp = 0; kp < 32; ++kp) {
                ull a0 = ld2s(&s.Lc[tk   ][2*kp]);
                ull a1 = ld2s(&s.Lc[tk+16][2*kp]);
                ull a2 = ld2s(&s.Lc[tk+32][2*kp]);
                ull a3 = ld2s(&s.Lc[tk+48][2*kp]);
                ull b0 = ld2s(&s.F[td   ][2*kp]);
                ull b1 = ld2s(&s.F[td+32][2*kp]);
                fma2(acc[0][0],a0,b0); fma2(acc[0][1],a0,b1);
                fma2(acc[1][0],a1,b0); fma2(acc[1][1],a1,b1);
                fma2(acc[2][0],a2,b0); fma2(acc[2][1],a2,b1);
                fma2(acc[3][0],a3,b0); fma2(acc[3][1],a3,b1);
            }
            #pragma unroll
            for (int r = 0; r < 4; ++r) {
                s.Gk[tk+16*r][td   ] = hsum2(acc[r][0]);
                s.Gk[tk+16*r][td+32] = hsum2(acc[r][1]);
            }
            if (tid < NS) {
                ull rc = 0ULL;
                #pragma unroll 4
                for (int kp = 0; kp < 32; ++kp)
                    fma2(rc, ld2s(&s.x[2*kp]), ld2s(&s.F[tid][2*kp]));
                s.row0[tid] = hsum2(rc);
            }
            if (tid < MO) s.yobs[tid] = yreg;
        }
        __syncthreads();

        // ======== phase 3: sf element-wise, stored transposed into dxT ========
        for (int idx = tid; idx < 130*NS; idx += NT) {
            int r = idx >> 6, d = idx & 63;
            float v;
            if (r == 129) v = 0.0f;
            else {
                float base = s.x[d], arg = s.row0[d];
                if (r >= 1) {
                    int k = (r <= NS) ? r - 1 : r - 1 - NS;
                    float lv = s.Lc[k][d], gv = s.Gk[k][d];
                    if (r <= NS) { base += lv; arg += gv; }
                    else         { base -= lv; arg -= gv; }
                }
                v = base + DTC * tanh_fast(arg);
            }
            s.dxT[d][r] = v;
        }
        __syncthreads();

        // ======== phase 4: xp via intra-warp reduce (1 barrier) ========
        {
            int d = tid >> 3, g = tid & 7;
            float acc0 = 0.f, acc1 = 0.f;
            for (int k = g; k <= 120; k += 16) {
                acc0 += s.dxT[d][k];
                acc1 += s.dxT[d][k+8];
            }
            if (g == 0) acc0 += s.dxT[d][128];
            float v = acc0 + acc1;
            v += __shfl_down_sync(0xffffffffu, v, 4, 8);
            v += __shfl_down_sync(0xffffffffu, v, 2, 8);
            v += __shfl_down_sync(0xffffffffu, v, 1, 8);
            if (g == 0) s.xp[d] = CW * v + WMD * s.dxT[d][0];
        }
        __syncthreads();

        // ======== phase 5: center dxT in place | warp0: innov = y - H@xp ========
        if (tid < 32) {
            ull acc = 0ULL;
            #pragma unroll 4
            for (int kp = 0; kp < 32; ++kp)
                fma2(acc, ld2s(&s.H[tid][2*kp]), ld2s(&s.xp[2*kp]));
            s.innov[tid] = s.yobs[tid] - hsum2(acc);
        } else {
            for (int idx = tid - 32; idx < 130*NS; idx += NT - 32) {
                int d = idx / 130, k = idx - d * 130;
                float v = (k < 129) ? s.dxT[d][k] - s.xp[d] : 0.0f;
                s.dxT[d][k] = v;
            }
        }
        __syncthreads();

        // ======== phase 6: dzT = H @ dx ========
        {
            int ti = tid & 15, g = tid >> 4;   // g 0..31
            ull a00=0ULL,a01=0ULL,a10=0ULL,a11=0ULL, e0=0ULL, e1=0ULL;
            bool extra = (g == 31);
            for (int d = 0; d < NS; ++d) {
                ull h0 = pk2(s.H[ti   ][d]);
                ull h1 = pk2(s.H[ti+16][d]);
                ull b0 = ld2s(&s.dxT[d][2*g]);
                ull b1 = ld2s(&s.dxT[d][2*(g+32)]);
                fma2(a00,h0,b0); fma2(a01,h0,b1);
                fma2(a10,h1,b0); fma2(a11,h1,b1);
                if (extra) {
                    ull b2 = ld2s(&s.dxT[d][128]);
                    fma2(e0,h0,b2); fma2(e1,h1,b2);
                }
            }
            st2s(&s.dzT[ti   ][2*g],      a00);
            st2s(&s.dzT[ti   ][2*(g+32)], a01);
            st2s(&s.dzT[ti+16][2*g],      a10);
            st2s(&s.dzT[ti+16][2*(g+32)], a11);
            if (extra) {
                st2s(&s.dzT[ti   ][128], e0);
                st2s(&s.dzT[ti+16][128], e1);
            }
        }
        __syncthreads();

        // ======== phase 7: Pz gram (2 outputs/thread) ========
        {
            int ti = tid & 15, tj = tid >> 4;   // tj 0..31
            ull a0 = 0ULL, a1 = 0ULL;
            #pragma unroll 2
            for (int kp = 0; kp < 65; ++kp) {
                ull b  = ld2s(&s.dzT[tj][2*kp]);
                fma2(a0, ld2s(&s.dzT[ti   ][2*kp]), b);
                fma2(a1, ld2s(&s.dzT[ti+16][2*kp]), b);
            }
            float bz = s.dzT[tj][0];
            s.Pz[ti   ][tj] = CW*hsum2(a0) + WDIFF * s.dzT[ti   ][0]*bz + s.Rs[ti   ][tj];
            s.Pz[ti+16][tj] = CW*hsum2(a1) + WDIFF * s.dzT[ti+16][0]*bz + s.Rs[ti+16][tj];
        }
        __syncthreads();

        // ======== phase 8: warp0 chol32(Pz) | 4x4-tile P_pred + Pxz grams ========
        if (tid < 32) {
            int lane = tid;
            for (int j = 0; j < MO; ++j) {
                float c = 0.0f;
                if (lane >= j) {
                    c = s.Pz[lane][j];
                    float c0=0.f, c1=0.f; int k = 0;
                    for (; k + 1 < j; k += 2) {
                        c0 += s.Pz[lane][k]   * s.Pz[j][k];
                        c1 += s.Pz[lane][k+1] * s.Pz[j][k+1];
                    }
                    if (k < j) c0 += s.Pz[lane][k] * s.Pz[j][k];
                    c -= c0 + c1;
                }
                float cj = __shfl_sync(0xffffffffu, c, j);
                float d = sqrtf(cj);
                if (lane == j)      { s.Pz[j][j] = d; s.zinv[j] = 1.0f / d; }
                else if (lane > j)  { s.Pz[lane][j] = c / d; }
                __syncwarp();
            }
        } else if (tid < 416) {
            int idx = tid - 32;
            if (idx < 256) {
                // P_pred 4x4: rows ti+16r, cols tj+16c (broadcast-friendly lanes)
                int ti = idx & 15, tj = idx >> 4;
                ull acc[4][4];
                #pragma unroll
                for (int r = 0; r < 4; ++r)
                    #pragma unroll
                    for (int c = 0; c < 4; ++c) acc[r][c] = 0ULL;
                #pragma unroll 2
                for (int kp = 0; kp < 65; ++kp) {
                    ull a0 = ld2s(&s.dxT[ti   ][2*kp]);
                    ull a1 = ld2s(&s.dxT[ti+16][2*kp]);
                    ull a2 = ld2s(&s.dxT[ti+32][2*kp]);
                    ull a3 = ld2s(&s.dxT[ti+48][2*kp]);
                    ull b0 = ld2s(&s.dxT[tj   ][2*kp]);
                    ull b1 = ld2s(&s.dxT[tj+16][2*kp]);
                    ull b2 = ld2s(&s.dxT[tj+32][2*kp]);
                    ull b3 = ld2s(&s.dxT[tj+48][2*kp]);
                    fma2(acc[0][0],a0,b0); fma2(acc[0][1],a0,b1); fma2(acc[0][2],a0,b2); fma2(acc[0][3],a0,b3);
                    fma2(acc[1][0],a1,b0); fma2(acc[1][1],a1,b1); fma2(acc[1][2],a1,b2); fma2(acc[1][3],a1,b3);
                    fma2(acc[2][0],a2,b0); fma2(acc[2][1],a2,b1); fma2(acc[2][2],a2,b2); fma2(acc[2][3],a2,b3);
                    fma2(acc[3][0],a3,b0); fma2(acc[3][1],a3,b1); fma2(acc[3][2],a3,b2); fma2(acc[3][3],a3,b3);
                }
                #pragma unroll
                for (int r = 0; r < 4; ++r)
                    #pragma unroll
                    for (int c = 0; c < 4; ++c) {
                        int i = ti + 16*r, j = tj + 16*c;
                        s.P[i][j] = CW*hsum2(acc[r][c])
                                  + WDIFF * s.dxT[i][0]*s.dxT[j][0] + s.Qs[i][j];
                    }
            } else {
                // Pxz 4x4: rows ti+16r, cols tj+8c
                int q = idx - 256;
                int ti = q & 15, tj = q >> 4;   // tj 0..7
                ull acc[4][4];
                #pragma unroll
                for (int r = 0; r < 4; ++r)
                    #pragma unroll
                    for (int c = 0; c < 4; ++c) acc[r][c] = 0ULL;
                #pragma unroll 2
                for (int kp = 0; kp < 65; ++kp) {
                    ull a0 = ld2s(&s.dxT[ti   ][2*kp]);
                    ull a1 = ld2s(&s.dxT[ti+16][2*kp]);
                    ull a2 = ld2s(&s.dxT[ti+32][2*kp]);
                    ull a3 = ld2s(&s.dxT[ti+48][2*kp]);
                    ull b0 = ld2s(&s.dzT[tj   ][2*kp]);
                    ull b1 = ld2s(&s.dzT[tj+ 8][2*kp]);
                    ull b2 = ld2s(&s.dzT[tj+16][2*kp]);
                    ull b3 = ld2s(&s.dzT[tj+24][2*kp]);
                    fma2(acc[0][0],a0,b0); fma2(acc[0][1],a0,b1); fma2(acc[0][2],a0,b2); fma2(acc[0][3],a0,b3);
                    fma2(acc[1][0],a1,b0); fma2(acc[1][1],a1,b1); fma2(acc[1][2],a1,b2); fma2(acc[1][3],a1,b3);
                    fma2(acc[2][0],a2,b0); fma2(acc[2][1],a2,b1); fma2(acc[2][2],a2,b2); fma2(acc[2][3],a2,b3);
                    fma2(acc[3][0],a3,b0); fma2(acc[3][1],a3,b1); fma2(acc[3][2],a3,b2); fma2(acc[3][3],a3,b3);
                }
                #pragma unroll
                for (int r = 0; r < 4; ++r)
                    #pragma unroll
                    for (int c = 0; c < 4; ++c) {
                        int i = ti + 16*r, m = tj + 8*c;
                        s.Pxz[i][m] = CW*hsum2(acc[r][c])
                                    + WDIFF * s.dxT[i][0]*s.dzT[m][0];
                    }
            }
        }
        __syncthreads();

        // ======== phase 9: forward solves L*[U|w] = [Pxz^T|innov] ========
        if (tid < NS + 1) {
            float v[MO];
            if (tid < NS) {
                #pragma unroll
                for (int m = 0; m < MO; ++m) v[m] = s.Pxz[tid][m];
            } else {
                #pragma unroll
                for (int m = 0; m < MO; ++m) v[m] = s.innov[m];
            }
            #pragma unroll
            for (int i = 0; i < MO; ++i) {
                float c0 = v[i], c1 = 0.0f;
                #pragma unroll
                for (int j = 0; j + 1 < i; j += 2) {
                    c0 -= s.Pz[i][j]   * v[j];
                    c1 += s.Pz[i][j+1] * v[j+1];
                }
                if (i & 1) c0 -= s.Pz[i][i-1] * v[i-1];
                v[i] = (c0 - c1) * s.zinv[i];
            }
            if (tid < NS) {
                #pragma unroll
                for (int m = 0; m < MO; ++m) s.Usm[tid][m] = v[m];
            } else {
                #pragma unroll
                for (int m = 0; m < MO; ++m) s.wsol[m] = v[m];
            }
        }
        __syncthreads();

        // ======== phase 10: x_new + (P_new = P - U^T U) -> next Achol ========
        if (tid < NS) {
            float xn = s.xp[tid];
            #pragma unroll
            for (int m = 0; m < MO; ++m) xn += s.Usm[tid][m] * s.wsol[m];
            s.x[tid] = xn;
            size_t oidx = ((size_t)traj * TSTEPS + t) * NS + tid;
            if (write_xs) out[oidx] = xn;
            float de = xn - gX[oidx];
            mse_acc += de * de;
        }
        if (tid < 256) {
            int ti = tid & 15, tj = tid >> 4;   // tj 0..15
            ull acc[4][4];
            #pragma unroll
            for (int r = 0; r < 4; ++r)
                #pragma unroll
                for (int c = 0; c < 4; ++c) acc[r][c] = 0ULL;
            #pragma unroll 4
            for (int mp = 0; mp < 16; ++mp) {
                ull a0 = ld2s(&s.Usm[ti   ][2*mp]);
                ull a1 = ld2s(&s.Usm[ti+16][2*mp]);
                ull a2 = ld2s(&s.Usm[ti+32][2*mp]);
                ull a3 = ld2s(&s.Usm[ti+48][2*mp]);
                ull b0 = ld2s(&s.Usm[tj   ][2*mp]);
                ull b1 = ld2s(&s.Usm[tj+16][2*mp]);
                ull b2 = ld2s(&s.Usm[tj+32][2*mp]);
                ull b3 = ld2s(&s.Usm[tj+48][2*mp]);
                fma2(acc[0][0],a0,b0); fma2(acc[0][1],a0,b1); fma2(acc[0][2],a0,b2); fma2(acc[0][3],a0,b3);
                fma2(acc[1][0],a1,b0); fma2(acc[1][1],a1,b1); fma2(acc[1][2],a1,b2); fma2(acc[1][3],a1,b3);
                fma2(acc[2][0],a2,b0); fma2(acc[2][1],a2,b1); fma2(acc[2][2],a2,b2); fma2(acc[2][3],a2,b3);
                fma2(acc[3][0],a3,b0); fma2(acc[3][1],a3,b1); fma2(acc[3][2],a3,b2); fma2(acc[3][3],a3,b3);
            }
            #pragma unroll
            for (int r = 0; r < 4; ++r)
                #pragma unroll
                for (int c = 0; c < 4; ++c) {
                    int i = ti + 16*r, j = tj + 16*c;
                    float pv = s.P[i][j] - hsum2(acc[r][c]);
                    s.Achol[j][i] = NLAM * (pv + ((i == j) ? 1e-8f : 0.0f));
                    if (write_ps)
                        out[XS_OFF + (((size_t)traj * TSTEPS + t) << 12) + (size_t)i*NS + j] = pv;
                }
        }
        __syncthreads();
    }

    // ---- per-trajectory MSE + merged finalize ----
    {
        float v = (tid < NS) ? mse_acc : 0.0f;
        for (int o = 16; o > 0; o >>= 1) v += __shfl_down_sync(0xffffffffu, v, o);
        if ((tid & 31) == 0) s.red[tid >> 5] = v;
        __syncthreads();
        if (tid == 0) {
            g_mse[traj] = (s.red[0] + s.red[1]) * (1.0f / (float)(TSTEPS * NS));
            __threadfence();
            unsigned int prev = atomicAdd(&g_ctr, 1u);
            if (prev == NTRAJ - 1) {
                __threadfence();
                float tot = 0.0f;
                for (int i = 0; i < NTRAJ; ++i) tot += g_mse[i];
                float lin = tot / (float)NTRAJ;
                float db = 10.0f * log10f(lin);
                const unsigned long long XS = XS_OFF, PS = PS_SZ;
                if (osz >= XS + PS + 2ULL)      { out[XS+PS] = lin; out[XS+PS+1ULL] = db; }
                else if (osz == XS + 2ULL)      { out[XS] = lin; out[XS+1ULL] = db; }
                else if (osz == 2ULL)           { out[0] = lin; out[1] = db; }
                else if (osz == 1ULL)           { out[0] = db; }
                atomicExch(&g_ctr, 0u);
            }
        }
    }
}

extern "C" void kernel_launch(void* const* d_in, const int* in_sizes, int n_in,
                              void* d_out, int out_size)
{
    const float* X = (const float*)d_in[0];
    const float* Y = (const float*)d_in[1];
    const float* F = (const float*)d_in[2];
    const float* H = (const float*)d_in[3];
    const float* Q = (const float*)d_in[4];
    const float* R = (const float*)d_in[5];
    float* out = (float*)d_out;

    unsigned long long os = (unsigned long long)(long long)out_size;
    int wxs = (os >= XS_OFF) ? 1 : 0;
    int wps = (os >= XS_OFF + PS_SZ) ? 1 : 0;

    cudaFuncSetAttribute(ukf_kernel, cudaFuncAttributeMaxDynamicSharedMemorySize,
                         (int)sizeof(SM));
    ukf_kernel<<<NTRAJ, NT, sizeof(SM)>>>(X, Y, F, H, Q, R, out, wxs, wps, os);
}

// round 13
// speedup vs baseline: 1.3843x; 1.0800x over previous
#include <cuda_runtime.h>
#include <cstdint>
#include <cstddef>

#define NS 64
#define MO 32
#define NSIG 129
#define TSTEPS 250
#define NTRAJ 128
#define NT 512
#define DTC 0.02f
#define NLAM 63.0f
#define CW (0.5f/63.0f)
#define WM0 (-1.0f/63.0f)
#define WC0 (2.0f - 1.0f/63.0f)
#define WDIFF (WC0 - CW)
#define WMD (WM0 - CW)
#define XS_OFF 2048000ULL
#define PS_SZ  131072000ULL

typedef unsigned long long ull;

__device__ __forceinline__ void fma2(ull &d, ull a, ull b) {
    asm("fma.rn.f32x2 %0, %1, %2, %0;" : "+l"(d) : "l"(a), "l"(b));
}
__device__ __forceinline__ float hsum2(ull v) {
    return __uint_as_float((unsigned)v) + __uint_as_float((unsigned)(v >> 32));
}
__device__ __forceinline__ ull ld2s(const float* p) { return *reinterpret_cast<const ull*>(p); }
__device__ __forceinline__ void st2s(float* p, ull v) { *reinterpret_cast<ull*>(p) = v; }
__device__ __forceinline__ ull pk2(float x) {
    ull r; asm("mov.b64 %0, {%1, %1};" : "=l"(r) : "f"(x)); return r;
}
__device__ __forceinline__ float tanh_fast(float x) {
    float r; asm("tanh.approx.f32 %0, %1;" : "=f"(r) : "f"(x)); return r;
}

struct SM {
    float F[NS][66];
    float H[MO][66];
    float Qs[NS][66];
    float Rs[MO][33];
    float P[NS][66];
    float Achol[NS][66];   // column-major: Achol[j][i] = NLAM*(P+eps)
    float Lc[NS][66];      // Lc[k][d] = L[d][k]
    float Gk[NS][66];      // Gk[k][d] = sum_e Lc[k][e]*F[d][e]
    float dxT[NS][130];    // raw sf, then centered; col 129 = pad(0)
    float dzT[MO][130];
    float Pz[MO][33];
    float Pxz[NS][34];
    float Usm[NS][34];
    float x[NS], xp[NS], innov[MO], zinv[MO], wsol[MO], row0[NS], yobs[MO];
    float red[16];
    unsigned char tri8[136];   // packed (ti | tj<<4) for ti<=tj triangular tiles
};

__device__ float g_mse[NTRAJ];
__device__ unsigned int g_ctr = 0;

__global__ __launch_bounds__(NT, 1)
void ukf_kernel(const float* __restrict__ gX, const float* __restrict__ gY,
                const float* __restrict__ gF, const float* __restrict__ gH,
                const float* __restrict__ gQ, const float* __restrict__ gR,
                float* __restrict__ out, int write_xs, int write_ps,
                unsigned long long osz)
{
    extern __shared__ unsigned char smem_raw[];
    SM& s = *reinterpret_cast<SM*>(smem_raw);
    const int tid = threadIdx.x;
    const int traj = blockIdx.x;

    // ---- init ----
    for (int idx = tid; idx < NS*NS; idx += NT) {
        int i = idx >> 6, j = idx & 63;
        s.F[i][j]  = gF[idx];
        s.Qs[i][j] = gQ[idx];
        s.Achol[j][i] = (i == j) ? NLAM * (1e-5f + 1e-8f) : 0.0f;
    }
    for (int idx = tid; idx < MO*NS; idx += NT) {
        int i = idx >> 6, j = idx & 63;
        s.H[i][j] = gH[idx];
    }
    for (int idx = tid; idx < MO*MO; idx += NT) {
        int i = idx >> 5, j = idx & 31;
        s.Rs[i][j] = gR[idx];
    }
    if (tid < 136) {
        int a = tid, ti = 0;
        while (a >= 16 - ti) { a -= 16 - ti; ++ti; }
        s.tri8[tid] = (unsigned char)(ti | ((ti + a) << 4));
    }
    if (tid < NS) s.x[tid] = 0.0f;
    float mse_acc = 0.0f;

    for (int t = 0; t < TSTEPS; ++t) {
        // ======== phase 1: rank-2 chol64, scalar loop only (32 barriers) ========
        {
            const int kk = tid & 63, pp = tid >> 6;   // pp 0..7
            #pragma unroll 1
            for (int j = 0; j < NS - 2; j += 2) {
                __syncthreads();
                if (kk > j + 1) {
                    float a00 = s.Achol[j][j];
                    float a01 = s.Achol[j][j+1];
                    float inv00 = 1.0f / a00;
                    float r01 = a01 * inv00;
                    float a11p = s.Achol[j+1][j+1] - a01 * r01;
                    float inv11 = 1.0f / a11p;
                    float b0 = s.Achol[j][kk];
                    float b1 = s.Achol[j+1][kk] - r01 * b0;
                    float c0 = b0 * inv00;
                    float c1 = b1 * inv11;
                    ull m0 = pk2(-(c0 - c1 * r01));
                    ull m1 = pk2(-c1);
                    #pragma unroll
                    for (int p = pp; p < 32; p += 8) {
                        if (2*p + 1 >= kk - 1) {
                            ull cur = ld2s(&s.Achol[kk][2*p]);
                            fma2(cur, ld2s(&s.Achol[j  ][2*p]), m0);
                            fma2(cur, ld2s(&s.Achol[j+1][2*p]), m1);
                            st2s(&s.Achol[kk][2*p], cur);
                        }
                    }
                }
            }
        }
        __syncthreads();
        // ---- deferred L extraction: Lc[j][i] from final Achol columns ----
        for (int idx = tid; idx < NS*NS; idx += NT) {
            int j = idx >> 6, i = idx & 63;
            int j0 = j & ~1;
            float a00 = s.Achol[j0][j0];
            float val;
            if ((j & 1) == 0) {
                val = (i >= j) ? s.Achol[j][i] / sqrtf(a00) : 0.0f;
            } else {
                float a01 = s.Achol[j0][j];
                float r01 = a01 / a00;
                float a11p = s.Achol[j][j] - a01 * r01;
                val = (i >= j) ? (s.Achol[j][i] - r01 * s.Achol[j0][i]) / sqrtf(a11p) : 0.0f;
            }
            s.Lc[j][i] = val;
        }
        __syncthreads();

        // ======== phase 2: Gk = Lc @ F^T; row0 = F@x; prefetch y ========
        {
            float yreg = 0.0f;
            if (tid < MO) yreg = gY[(size_t)traj * TSTEPS * MO + (size_t)t * MO + tid];
            int tk = tid & 15, td = tid >> 4;   // td 0..31
            ull acc[4][2];
            #pragma unroll
            for (int r = 0; r < 4; ++r) { acc[r][0] = 0ULL; acc[r][1] = 0ULL; }
            #pragma unroll 4
            for (int kp = 0; kp < 32; ++kp) {
                ull a0 = ld2s(&s.Lc[tk   ][2*kp]);
                ull a1 = ld2s(&s.Lc[tk+16][2*kp]);
                ull a2 = ld2s(&s.Lc[tk+32][2*kp]);
                ull a3 = ld2s(&s.Lc[tk+48][2*kp]);
                ull b0 = ld2s(&s.F[td   ][2*kp]);
                ull b1 = ld2s(&s.F[td+32][2*kp]);
                fma2(acc[0][0],a0,b0); fma2(acc[0][1],a0,b1);
                fma2(acc[1][0],a1,b0); fma2(acc[1][1],a1,b1);
                fma2(acc[2][0],a2,b0); fma2(acc[2][1],a2,b1);
                fma2(acc[3][0],a3,b0); fma2(acc[3][1],a3,b1);
            }
            #pragma unroll
            for (int r = 0; r < 4; ++r) {
                s.Gk[tk+16*r][td   ] = hsum2(acc[r][0]);
                s.Gk[tk+16*r][td+32] = hsum2(acc[r][1]);
            }
            if (tid < NS) {
                ull rc = 0ULL;
                #pragma unroll 4
                for (int kp = 0; kp < 32; ++kp)
                    fma2(rc, ld2s(&s.x[2*kp]), ld2s(&s.F[tid][2*kp]));
                s.row0[tid] = hsum2(rc);
            }
            if (tid < MO) s.yobs[tid] = yreg;
        }
        __syncthreads();

        // ======== phase 3: sf element-wise, stored transposed into dxT ========
        for (int idx = tid; idx < 130*NS; idx += NT) {
            int r = idx >> 6, d = idx & 63;
            float v;
            if (r == 129) v = 0.0f;
            else {
                float base = s.x[d], arg = s.row0[d];
                if (r >= 1) {
                    int k = (r <= NS) ? r - 1 : r - 1 - NS;
                    float lv = s.Lc[k][d], gv = s.Gk[k][d];
                    if (r <= NS) { base += lv; arg += gv; }
                    else         { base -= lv; arg -= gv; }
                }
                v = base + DTC * tanh_fast(arg);
            }
            s.dxT[d][r] = v;
        }
        __syncthreads();

        // ======== phase 4: xp via intra-warp reduce (1 barrier) ========
        {
            int d = tid >> 3, g = tid & 7;
            float acc0 = 0.f, acc1 = 0.f;
            for (int k = g; k <= 120; k += 16) {
                acc0 += s.dxT[d][k];
                acc1 += s.dxT[d][k+8];
            }
            if (g == 0) acc0 += s.dxT[d][128];
            float v = acc0 + acc1;
            v += __shfl_down_sync(0xffffffffu, v, 4, 8);
            v += __shfl_down_sync(0xffffffffu, v, 2, 8);
            v += __shfl_down_sync(0xffffffffu, v, 1, 8);
            if (g == 0) s.xp[d] = CW * v + WMD * s.dxT[d][0];
        }
        __syncthreads();

        // ======== phase 5: center dxT in place | warp0: innov = y - H@xp ========
        if (tid < 32) {
            ull acc = 0ULL;
            #pragma unroll 4
            for (int kp = 0; kp < 32; ++kp)
                fma2(acc, ld2s(&s.H[tid][2*kp]), ld2s(&s.xp[2*kp]));
            s.innov[tid] = s.yobs[tid] - hsum2(acc);
        } else {
            for (int idx = tid - 32; idx < 130*NS; idx += NT - 32) {
                int d = idx / 130, k = idx - d * 130;
                float v = (k < 129) ? s.dxT[d][k] - s.xp[d] : 0.0f;
                s.dxT[d][k] = v;
            }
        }
        __syncthreads();

        // ======== phase 6: dzT = H @ dx ========
        {
            int ti = tid & 15, g = tid >> 4;   // g 0..31
            ull a00=0ULL,a01=0ULL,a10=0ULL,a11=0ULL, e0=0ULL, e1=0ULL;
            bool extra = (g == 31);
            for (int d = 0; d < NS; ++d) {
                ull h0 = pk2(s.H[ti   ][d]);
                ull h1 = pk2(s.H[ti+16][d]);
                ull b0 = ld2s(&s.dxT[d][2*g]);
                ull b1 = ld2s(&s.dxT[d][2*(g+32)]);
                fma2(a00,h0,b0); fma2(a01,h0,b1);
                fma2(a10,h1,b0); fma2(a11,h1,b1);
                if (extra) {
                    ull b2 = ld2s(&s.dxT[d][128]);
                    fma2(e0,h0,b2); fma2(e1,h1,b2);
                }
            }
            st2s(&s.dzT[ti   ][2*g],      a00);
            st2s(&s.dzT[ti   ][2*(g+32)], a01);
            st2s(&s.dzT[ti+16][2*g],      a10);
            st2s(&s.dzT[ti+16][2*(g+32)], a11);
            if (extra) {
                st2s(&s.dzT[ti   ][128], e0);
                st2s(&s.dzT[ti+16][128], e1);
            }
        }
        __syncthreads();

        // ======== phase 7: Pz gram (2 outputs/thread) ========
        {
            int ti = tid & 15, tj = tid >> 4;   // tj 0..31
            ull a0 = 0ULL, a1 = 0ULL;
            #pragma unroll 2
            for (int kp = 0; kp < 65; ++kp) {
                ull b  = ld2s(&s.dzT[tj][2*kp]);
                fma2(a0, ld2s(&s.dzT[ti   ][2*kp]), b);
                fma2(a1, ld2s(&s.dzT[ti+16][2*kp]), b);
            }
            float bz = s.dzT[tj][0];
            s.Pz[ti   ][tj] = CW*hsum2(a0) + WDIFF * s.dzT[ti   ][0]*bz + s.Rs[ti   ][tj];
            s.Pz[ti+16][tj] = CW*hsum2(a1) + WDIFF * s.dzT[ti+16][0]*bz + s.Rs[ti+16][tj];
        }
        __syncthreads();

        // ======== phase 8: warp0 chol32(Pz) | sym P_pred (136) + Pxz (128) ========
        if (tid < 32) {
            int lane = tid;
            for (int j = 0; j < MO; ++j) {
                float c = 0.0f;
                if (lane >= j) {
                    c = s.Pz[lane][j];
                    float c0=0.f, c1=0.f; int k = 0;
                    for (; k + 1 < j; k += 2) {
                        c0 += s.Pz[lane][k]   * s.Pz[j][k];
                        c1 += s.Pz[lane][k+1] * s.Pz[j][k+1];
                    }
                    if (k < j) c0 += s.Pz[lane][k] * s.Pz[j][k];
                    c -= c0 + c1;
                }
                float cj = __shfl_sync(0xffffffffu, c, j);
                float d = sqrtf(cj);
                if (lane == j)      { s.Pz[j][j] = d; s.zinv[j] = 1.0f / d; }
                else if (lane > j)  { s.Pz[lane][j] = c / d; }
                __syncwarp();
            }
        } else if (tid < 296) {
            int idx = tid - 32;
            if (idx < 136) {
                // symmetric P_pred tile (ti<=tj): compute once, mirror-write
                int pr = s.tri8[idx];
                int ti = pr & 15, tj = pr >> 4;
                ull acc[4][4];
                #pragma unroll
                for (int r = 0; r < 4; ++r)
                    #pragma unroll
                    for (int c = 0; c < 4; ++c) acc[r][c] = 0ULL;
                #pragma unroll 2
                for (int kp = 0; kp < 65; ++kp) {
                    ull a0 = ld2s(&s.dxT[ti   ][2*kp]);
                    ull a1 = ld2s(&s.dxT[ti+16][2*kp]);
                    ull a2 = ld2s(&s.dxT[ti+32][2*kp]);
                    ull a3 = ld2s(&s.dxT[ti+48][2*kp]);
                    ull b0 = ld2s(&s.dxT[tj   ][2*kp]);
                    ull b1 = ld2s(&s.dxT[tj+16][2*kp]);
                    ull b2 = ld2s(&s.dxT[tj+32][2*kp]);
                    ull b3 = ld2s(&s.dxT[tj+48][2*kp]);
                    fma2(acc[0][0],a0,b0); fma2(acc[0][1],a0,b1); fma2(acc[0][2],a0,b2); fma2(acc[0][3],a0,b3);
                    fma2(acc[1][0],a1,b0); fma2(acc[1][1],a1,b1); fma2(acc[1][2],a1,b2); fma2(acc[1][3],a1,b3);
                    fma2(acc[2][0],a2,b0); fma2(acc[2][1],a2,b1); fma2(acc[2][2],a2,b2); fma2(acc[2][3],a2,b3);
                    fma2(acc[3][0],a3,b0); fma2(acc[3][1],a3,b1); fma2(acc[3][2],a3,b2); fma2(acc[3][3],a3,b3);
                }
                #pragma unroll
                for (int r = 0; r < 4; ++r)
                    #pragma unroll
                    for (int c = 0; c < 4; ++c) {
                        int i = ti + 16*r, j = tj + 16*c;
                        float g = CW*hsum2(acc[r][c]) + WDIFF * s.dxT[i][0]*s.dxT[j][0];
                        s.P[i][j] = g + s.Qs[i][j];
                        if (ti != tj) s.P[j][i] = g + s.Qs[j][i];
                    }
            } else {
                // Pxz 4x4: rows ti+16r, cols tj+8c
                int q = idx - 136;
                int ti = q & 15, tj = q >> 4;   // tj 0..7
                ull acc[4][4];
                #pragma unroll
                for (int r = 0; r < 4; ++r)
                    #pragma unroll
                    for (int c = 0; c < 4; ++c) acc[r][c] = 0ULL;
                #pragma unroll 2
                for (int kp = 0; kp < 65; ++kp) {
                    ull a0 = ld2s(&s.dxT[ti   ][2*kp]);
                    ull a1 = ld2s(&s.dxT[ti+16][2*kp]);
                    ull a2 = ld2s(&s.dxT[ti+32][2*kp]);
                    ull a3 = ld2s(&s.dxT[ti+48][2*kp]);
                    ull b0 = ld2s(&s.dzT[tj   ][2*kp]);
                    ull b1 = ld2s(&s.dzT[tj+ 8][2*kp]);
                    ull b2 = ld2s(&s.dzT[tj+16][2*kp]);
                    ull b3 = ld2s(&s.dzT[tj+24][2*kp]);
                    fma2(acc[0][0],a0,b0); fma2(acc[0][1],a0,b1); fma2(acc[0][2],a0,b2); fma2(acc[0][3],a0,b3);
                    fma2(acc[1][0],a1,b0); fma2(acc[1][1],a1,b1); fma2(acc[1][2],a1,b2); fma2(acc[1][3],a1,b3);
                    fma2(acc[2][0],a2,b0); fma2(acc[2][1],a2,b1); fma2(acc[2][2],a2,b2); fma2(acc[2][3],a2,b3);
                    fma2(acc[3][0],a3,b0); fma2(acc[3][1],a3,b1); fma2(acc[3][2],a3,b2); fma2(acc[3][3],a3,b3);
                }
                #pragma unroll
                for (int r = 0; r < 4; ++r)
                    #pragma unroll
                    for (int c = 0; c < 4; ++c) {
                        int i = ti + 16*r, m = tj + 8*c;
                        s.Pxz[i][m] = CW*hsum2(acc[r][c])
                                    + WDIFF * s.dxT[i][0]*s.dzT[m][0];
                    }
            }
        }
        __syncthreads();

        // ======== phase 9: forward solves L*[U|w] = [Pxz^T|innov] ========
        if (tid < NS + 1) {
            float v[MO];
            if (tid < NS) {
                #pragma unroll
                for (int m = 0; m < MO; ++m) v[m] = s.Pxz[tid][m];
            } else {
                #pragma unroll
                for (int m = 0; m < MO; ++m) v[m] = s.innov[m];
            }
            #pragma unroll
            for (int i = 0; i < MO; ++i) {
                float c0 = v[i], c1 = 0.0f;
                #pragma unroll
                for (int j = 0; j + 1 < i; j += 2) {
                    c0 -= s.Pz[i][j]   * v[j];
                    c1 += s.Pz[i][j+1] * v[j+1];
                }
                if (i & 1) c0 -= s.Pz[i][i-1] * v[i-1];
                v[i] = (c0 - c1) * s.zinv[i];
            }
            if (tid < NS) {
                #pragma unroll
                for (int m = 0; m < MO; ++m) s.Usm[tid][m] = v[m];
            } else {
                #pragma unroll
                for (int m = 0; m < MO; ++m) s.wsol[m] = v[m];
            }
        }
        __syncthreads();

        // ======== phase 10: x_new | sym UtU (136 tasks) -> next Achol ========
        if (tid < NS) {
            float xn = s.xp[tid];
            #pragma unroll
            for (int m = 0; m < MO; ++m) xn += s.Usm[tid][m] * s.wsol[m];
            s.x[tid] = xn;
            size_t oidx = ((size_t)traj * TSTEPS + t) * NS + tid;
            if (write_xs) out[oidx] = xn;
            float de = xn - gX[oidx];
            mse_acc += de * de;
        }
        if (tid >= 64 && tid < 200) {
            int idx = tid - 64;
            int pr = s.tri8[idx];
            int ti = pr & 15, tj = pr >> 4;
            ull acc[4][4];
            #pragma unroll
            for (int r = 0; r < 4; ++r)
                #pragma unroll
                for (int c = 0; c < 4; ++c) acc[r][c] = 0ULL;
            #pragma unroll 4
            for (int mp = 0; mp < 16; ++mp) {
                ull a0 = ld2s(&s.Usm[ti   ][2*mp]);
                ull a1 = ld2s(&s.Usm[ti+16][2*mp]);
                ull a2 = ld2s(&s.Usm[ti+32][2*mp]);
                ull a3 = ld2s(&s.Usm[ti+48][2*mp]);
                ull b0 = ld2s(&s.Usm[tj   ][2*mp]);
                ull b1 = ld2s(&s.Usm[tj+16][2*mp]);
                ull b2 = ld2s(&s.Usm[tj+32][2*mp]);
                ull b3 = ld2s(&s.Usm[tj+48][2*mp]);
                fma2(acc[0][0],a0,b0); fma2(acc[0][1],a0,b1); fma2(acc[0][2],a0,b2); fma2(acc[0][3],a0,b3);
                fma2(acc[1][0],a1,b0); fma2(acc[1][1],a1,b1); fma2(acc[1][2],a1,b2); fma2(acc[1][3],a1,b3);
                fma2(acc[2][0],a2,b0); fma2(acc[2][1],a2,b1); fma2(acc[2][2],a2,b2); fma2(acc[2][3],a2,b3);
                fma2(acc[3][0],a3,b0); fma2(acc[3][1],a3,b1); fma2(acc[3][2],a3,b2); fma2(acc[3][3],a3,b3);
            }
            #pragma unroll
            for (int r = 0; r < 4; ++r)
                #pragma unroll
                for (int c = 0; c < 4; ++c) {
                    int i = ti + 16*r, j = tj + 16*c;
                    float hv = hsum2(acc[r][c]);
                    float pv = s.P[i][j] - hv;
                    s.Achol[j][i] = NLAM * (pv + ((i == j) ? 1e-8f : 0.0f));
                    if (write_ps)
                        out[XS_OFF + (((size_t)traj * TSTEPS + t) << 12) + (size_t)i*NS + j] = pv;
                    if (ti != tj) {
                        float pv2 = s.P[j][i] - hv;
                        s.Achol[i][j] = NLAM * pv2;
                        if (write_ps)
                            out[XS_OFF + (((size_t)traj * TSTEPS + t) << 12) + (size_t)j*NS + i] = pv2;
                    }
                }
        }
        __syncthreads();
    }

    // ---- per-trajectory MSE + merged finalize ----
    {
        float v = (tid < NS) ? mse_acc : 0.0f;
        for (int o = 16; o > 0; o >>= 1) v += __shfl_down_sync(0xffffffffu, v, o);
        if ((tid & 31) == 0) s.red[tid >> 5] = v;
        __syncthreads();
        if (tid == 0) {
            g_mse[traj] = (s.red[0] + s.red[1]) * (1.0f / (float)(TSTEPS * NS));
            __threadfence();
            unsigned int prev = atomicAdd(&g_ctr, 1u);
            if (prev == NTRAJ - 1) {
                __threadfence();
                float tot = 0.0f;
                for (int i = 0; i < NTRAJ; ++i) tot += g_mse[i];
                float lin = tot / (float)NTRAJ;
                float db = 10.0f * log10f(lin);
                const unsigned long long XS = XS_OFF, PS = PS_SZ;
                if (osz >= XS + PS + 2ULL)      { out[XS+PS] = lin; out[XS+PS+1ULL] = db; }
                else if (osz == XS + 2ULL)      { out[XS] = lin; out[XS+1ULL] = db; }
                else if (osz == 2ULL)           { out[0] = lin; out[1] = db; }
                else if (osz == 1ULL)           { out[0] = db; }
                atomicExch(&g_ctr, 0u);
            }
        }
    }
}

extern "C" void kernel_launch(void* const* d_in, const int* in_sizes, int n_in,
                              void* d_out, int out_size)
{
    const float* X = (const float*)d_in[0];
    const float* Y = (const float*)d_in[1];
    const float* F = (const float*)d_in[2];
    const float* H = (const float*)d_in[3];
    const float* Q = (const float*)d_in[4];
    const float* R = (const float*)d_in[5];
    float* out = (float*)d_out;

    unsigned long long os = (unsigned long long)(long long)out_size;
    int wxs = (os >= XS_OFF) ? 1 : 0;
    int wps = (os >= XS_OFF + PS_SZ) ? 1 : 0;

    cudaFuncSetAttribute(ukf_kernel, cudaFuncAttributeMaxDynamicSharedMemorySize,
                         (int)sizeof(SM));
    ukf_kernel<<<NTRAJ, NT, sizeof(SM)>>>(X, Y, F, H, Q, R, out, wxs, wps, os);
}